// round 12
// baseline (speedup 1.0000x reference)
#include <cuda_runtime.h>
#include <cuda_bf16.h>

#define B_  8192
#define T_  200
#define IN_ 4
#define H_  16
#define L_  4
#define MLP_IN  (H_ * T_)   // 3200
#define MLP_HID 64
#define MLP_OUT 28
#define NCHUNK  16          // mlp1 K-chunks (200 rows each)

typedef unsigned long long ull;

// ---------------- scratch (no allocations allowed) ----------------
__device__ float g_h3[(long)MLP_IN * B_];                 // [m][b]
__device__ float g_partial[NCHUNK * MLP_HID * B_];        // [chunk][j][b]

// ---------------- packed f32x2 helpers ----------------
__device__ __forceinline__ ull pack2(float lo, float hi) {
    ull r; asm("mov.b64 %0, {%1, %2};" : "=l"(r) : "f"(lo), "f"(hi)); return r;
}
__device__ __forceinline__ void unpack2(ull v, float& lo, float& hi) {
    asm("mov.b64 {%0, %1}, %2;" : "=f"(lo), "=f"(hi) : "l"(v));
}
__device__ __forceinline__ ull ffma2(ull a, ull b, ull c) {
    ull d; asm("fma.rn.f32x2 %0, %1, %2, %3;" : "=l"(d) : "l"(a), "l"(b), "l"(c)); return d;
}

// ---------------- activations (fp32, overflow-safe, exact class) ----
__device__ __forceinline__ float sigmoidf_(float x) {
    return __fdividef(1.0f, 1.0f + __expf(-x));
}
__device__ __forceinline__ float tanhf_(float x) {
    // 2*sigmoid(2x)-1; x<<0: exp->inf, rcp->0, -1 OK; x>>0: exp->0, +1 OK
    return __fdividef(2.0f, 1.0f + __expf(-2.0f * x)) - 1.0f;
}

#define NAMED_BAR(id) asm volatile("bar.sync %0, 64;" :: "r"(id) : "memory")

// h ring buffer: float hbuf[parity(2)][layer(4)][eg(8)][row 20 (16 used, pad 4)]
#define HB_ROW  20
#define HB_SLOT (8 * HB_ROW)          // one (parity, layer) slot
#define HB_PAR  (4 * HB_SLOT)
// x slot: float xslot[parity(2)][eg(8)][8 (4 used + pad)]
#define XB_ROW  8
#define XB_PAR  (8 * XB_ROW)
#define HB_TOTAL (2 * HB_PAR + 2 * XB_PAR)

// =====================================================================
// Layer-pipelined LSTM: CTA = 4 warps = 4 layers, 8 batch elems.
// Warp l holds layer-l weights in registers; computes t = i - l.
// Chain named barriers (pairwise, 64 threads) instead of __syncthreads:
// warps slip +-1 iteration, interleaving activation/MUFU tails.
// x is prefetched one step ahead into smem by the l==0 warp (LDG hidden).
// 1024 CTAs x 128 threads, 2 CTAs/SM.
// =====================================================================
__global__ void __launch_bounds__(128, 2) lstm_kernel(
    const float* __restrict__ x,         // [B, T, IN]
    const float* __restrict__ Wih0,      // [64, 4]
    const float* __restrict__ Wih_rest,  // [3, 64, 16]
    const float* __restrict__ Whh,       // [4, 64, 16]
    const float* __restrict__ bih,       // [4, 64]
    const float* __restrict__ bhh)       // [4, 64]
{
    __shared__ __align__(16) float hbuf[HB_TOTAL];
    float* const xbuf = hbuf + 2 * HB_PAR;

    const int wid  = threadIdx.x >> 5;
    const int lane = threadIdx.x & 31;
    const int sub  = lane & 15;
    const int grp  = lane >> 4;
    const int l    = (wid + (int)blockIdx.x) & 3;        // layer rotation
    const int b0c  = (int)blockIdx.x * 8;                // CTA batch base
    const int b0   = b0c + grp * 4;                      // elems b0..b0+3

    for (int i = threadIdx.x; i < HB_TOTAL; i += blockDim.x) hbuf[i] = 0.0f;

    // ---- load this layer's weights into registers (k-pair packed) ----
    ull Wrec[4][8];   // [gate][kpair]
    ull Win[4][8];
    ull biasR[4];
#pragma unroll
    for (int g = 0; g < 4; ++g) {
        const float* rsrc = Whh + l * 1024 + (g * 16 + sub) * 16;
#pragma unroll
        for (int kc = 0; kc < 4; ++kc) {
            ulonglong2 v = *reinterpret_cast<const ulonglong2*>(rsrc + kc * 4);
            Wrec[g][2 * kc] = v.x; Wrec[g][2 * kc + 1] = v.y;
        }
        if (l == 0) {
            ulonglong2 v = *reinterpret_cast<const ulonglong2*>(Wih0 + (g * 16 + sub) * IN_);
            Win[g][0] = v.x; Win[g][1] = v.y;
#pragma unroll
            for (int kp = 2; kp < 8; ++kp) Win[g][kp] = 0ull;
        } else {
            const float* isrc = Wih_rest + (l - 1) * 1024 + (g * 16 + sub) * 16;
#pragma unroll
            for (int kc = 0; kc < 4; ++kc) {
                ulonglong2 v = *reinterpret_cast<const ulonglong2*>(isrc + kc * 4);
                Win[g][2 * kc] = v.x; Win[g][2 * kc + 1] = v.y;
            }
        }
        biasR[g] = pack2(bih[l * 64 + g * 16 + sub] + bhh[l * 64 + g * 16 + sub], 0.0f);
    }

    // initial x(0) into xbuf parity 1 (read at iter 0)
    if (threadIdx.x < 8) {
        float4 v = *reinterpret_cast<const float4*>(x + (long)(b0c + threadIdx.x) * (T_ * IN_));
        *reinterpret_cast<float4*>(xbuf + XB_PAR + threadIdx.x * XB_ROW) = v;
    }

    float c_own[4] = {0.0f, 0.0f, 0.0f, 0.0f};
    __syncthreads();

    for (int i = 0; i < T_ + L_ - 1; ++i) {
        const int p = i & 1;
        const int t = i - l;
        const bool active = ((unsigned)t < (unsigned)T_);

        if (active) {
            // l==0 warp prefetches x(t+1) for next iteration (hides LDG)
            if (l == 0 && lane < 8 && t + 1 < T_) {
                float4 v = *reinterpret_cast<const float4*>(
                    x + (long)(b0c + lane) * (T_ * IN_) + (t + 1) * IN_);
                *reinterpret_cast<float4*>(xbuf + p * XB_PAR + lane * XB_ROW) = v;
            }

            ull acc[4][4];   // [gate][e], halves = (even-k, odd-k) partials
#pragma unroll
            for (int g = 0; g < 4; ++g)
#pragma unroll
                for (int e = 0; e < 4; ++e) acc[g][e] = biasR[g];

            // ---- input projection ----
            if (l == 0) {
                const float* xsrc = xbuf + (1 - p) * XB_PAR;
#pragma unroll
                for (int e = 0; e < 4; ++e) {
                    ulonglong2 xv = *reinterpret_cast<const ulonglong2*>(
                        xsrc + (grp * 4 + e) * XB_ROW);
#pragma unroll
                    for (int g = 0; g < 4; ++g) {
                        acc[g][e] = ffma2(Win[g][0], xv.x, acc[g][e]);
                        acc[g][e] = ffma2(Win[g][1], xv.y, acc[g][e]);
                    }
                }
            } else {
                const float* hsrc = hbuf + (1 - p) * HB_PAR + (l - 1) * HB_SLOT;
#pragma unroll
                for (int kc = 0; kc < 4; ++kc) {
                    ulonglong2 hv[4];
#pragma unroll
                    for (int e = 0; e < 4; ++e)
                        hv[e] = *reinterpret_cast<const ulonglong2*>(
                            hsrc + (grp * 4 + e) * HB_ROW + kc * 4);
#pragma unroll
                    for (int g = 0; g < 4; ++g)
#pragma unroll
                        for (int e = 0; e < 4; ++e) {
                            acc[g][e] = ffma2(Win[g][2 * kc],     hv[e].x, acc[g][e]);
                            acc[g][e] = ffma2(Win[g][2 * kc + 1], hv[e].y, acc[g][e]);
                        }
                }
            }

            // ---- recurrent projection (own layer's h at t-1) ----
            {
                const float* hsrc = hbuf + (1 - p) * HB_PAR + l * HB_SLOT;
#pragma unroll
                for (int kc = 0; kc < 4; ++kc) {
                    ulonglong2 hv[4];
#pragma unroll
                    for (int e = 0; e < 4; ++e)
                        hv[e] = *reinterpret_cast<const ulonglong2*>(
                            hsrc + (grp * 4 + e) * HB_ROW + kc * 4);
#pragma unroll
                    for (int g = 0; g < 4; ++g)
#pragma unroll
                        for (int e = 0; e < 4; ++e) {
                            acc[g][e] = ffma2(Wrec[g][2 * kc],     hv[e].x, acc[g][e]);
                            acc[g][e] = ffma2(Wrec[g][2 * kc + 1], hv[e].y, acc[g][e]);
                        }
                }
            }

            // ---- horizontal add + activations + state update ----
            float hn[4];
#pragma unroll
            for (int e = 0; e < 4; ++e) {
                float lo, hi, ai, af, ag, ao;
                unpack2(acc[0][e], lo, hi); ai = lo + hi;
                unpack2(acc[1][e], lo, hi); af = lo + hi;
                unpack2(acc[2][e], lo, hi); ag = lo + hi;
                unpack2(acc[3][e], lo, hi); ao = lo + hi;
                float iv = sigmoidf_(ai);
                float fv = sigmoidf_(af);
                float gv = tanhf_(ag);
                float ov = sigmoidf_(ao);
                float cv = fmaf(fv, c_own[e], iv * gv);
                c_own[e] = cv;
                hn[e] = ov * tanhf_(cv);
            }

            // ---- publish new h into buf[p] slot l ----
            {
                float* hdst = hbuf + p * HB_PAR + l * HB_SLOT;
#pragma unroll
                for (int e = 0; e < 4; ++e)
                    hdst[(grp * 4 + e) * HB_ROW + sub] = hn[e];
            }
            if (l == L_ - 1) {
                float4 v = make_float4(hn[0], hn[1], hn[2], hn[3]);
                *reinterpret_cast<float4*>(g_h3 + (long)(t * 16 + sub) * B_ + b0) = v;
            }
        }

        // chain barriers: pair (l-1,l) uses id l. Lower id first; no deadlock.
        if (l > 0) NAMED_BAR(l);
        if (l < L_ - 1) NAMED_BAR(l + 1);
        __syncwarp();
    }
}

// =====================================================================
// MLP phase 1: partial hid sums over NCHUNK chunks of 200 rows.
// =====================================================================
__global__ void __launch_bounds__(256) mlp1_kernel(const float* __restrict__ W1)
{
    __shared__ float4 W1s[200 * 16];   // [mm][j4], 51.2 KB
    const int chunk = blockIdx.y;
    const int m0 = chunk * 200;
    {
        float* w = reinterpret_cast<float*>(W1s);
        for (int idx = threadIdx.x; idx < 200 * MLP_HID; idx += blockDim.x) {
            int mm = idx >> 6, j = idx & 63;
            w[idx] = W1[j * MLP_IN + m0 + mm];
        }
    }
    __syncthreads();

    const int jq = threadIdx.x & 3;
    const int bq = threadIdx.x >> 2;
    const int b0 = blockIdx.x * 256 + bq * 4;

    ull acc[8][4];
#pragma unroll
    for (int jp = 0; jp < 8; ++jp)
#pragma unroll
        for (int e = 0; e < 4; ++e) acc[jp][e] = 0ull;

    for (int mm = 0; mm < 200; ++mm) {
        float4 f = *reinterpret_cast<const float4*>(g_h3 + (long)(m0 + mm) * B_ + b0);
        ull f2[4] = { pack2(f.x, f.x), pack2(f.y, f.y), pack2(f.z, f.z), pack2(f.w, f.w) };
#pragma unroll
        for (int j4 = 0; j4 < 4; ++j4) {
            ulonglong2 wp = *reinterpret_cast<const ulonglong2*>(&W1s[mm * 16 + jq * 4 + j4]);
#pragma unroll
            for (int e = 0; e < 4; ++e) {
                acc[j4 * 2 + 0][e] = ffma2(wp.x, f2[e], acc[j4 * 2 + 0][e]);
                acc[j4 * 2 + 1][e] = ffma2(wp.y, f2[e], acc[j4 * 2 + 1][e]);
            }
        }
    }
#pragma unroll
    for (int jp = 0; jp < 8; ++jp) {
        float v0[4], v1[4];
#pragma unroll
        for (int e = 0; e < 4; ++e) unpack2(acc[jp][e], v0[e], v1[e]);
        int j = jq * 16 + jp * 2;
        *reinterpret_cast<float4*>(g_partial + ((long)chunk * MLP_HID + j) * B_ + b0) =
            make_float4(v0[0], v0[1], v0[2], v0[3]);
        *reinterpret_cast<float4*>(g_partial + ((long)chunk * MLP_HID + j + 1) * B_ + b0) =
            make_float4(v1[0], v1[1], v1[2], v1[3]);
    }
}

// =====================================================================
// MLP phase 2: reduce chunks, bias+relu, W2, write out [B, 28].
// =====================================================================
__global__ void __launch_bounds__(256) mlp2_kernel(
    const float* __restrict__ W2,   // [28, 64]
    const float* __restrict__ b1,   // [64]
    const float* __restrict__ b2,   // [28]
    float* __restrict__ out)        // [B, 28]
{
    __shared__ float W2s[MLP_OUT * MLP_HID];
    __shared__ float b1s[MLP_HID];
    __shared__ float b2s[MLP_OUT];
    for (int idx = threadIdx.x; idx < MLP_OUT * MLP_HID; idx += blockDim.x)
        W2s[idx] = W2[idx];
    if (threadIdx.x < MLP_HID) b1s[threadIdx.x] = b1[threadIdx.x];
    if (threadIdx.x < MLP_OUT) b2s[threadIdx.x] = b2[threadIdx.x];
    __syncthreads();

    const int b = blockIdx.x * 256 + threadIdx.x;
    float hid[MLP_HID];
#pragma unroll
    for (int j = 0; j < MLP_HID; ++j) hid[j] = b1s[j];

    for (int ch = 0; ch < NCHUNK; ++ch) {
#pragma unroll
        for (int j = 0; j < MLP_HID; ++j)
            hid[j] += g_partial[((long)ch * MLP_HID + j) * B_ + b];
    }
#pragma unroll
    for (int j = 0; j < MLP_HID; ++j) hid[j] = fmaxf(hid[j], 0.0f);

#pragma unroll
    for (int o = 0; o < MLP_OUT; ++o) {
        float a = b2s[o];
#pragma unroll
        for (int j = 0; j < MLP_HID; ++j)
            a = fmaf(hid[j], W2s[o * MLP_HID + j], a);
        out[(long)b * MLP_OUT + o] = a;
    }
}

// =====================================================================
extern "C" void kernel_launch(void* const* d_in, const int* in_sizes, int n_in,
                              void* d_out, int out_size)
{
    const float* x        = (const float*)d_in[0];
    const float* Wih0     = (const float*)d_in[1];
    const float* Wih_rest = (const float*)d_in[2];
    const float* Whh      = (const float*)d_in[3];
    const float* bih      = (const float*)d_in[4];
    const float* bhh      = (const float*)d_in[5];
    const float* W1       = (const float*)d_in[6];
    const float* b1       = (const float*)d_in[7];
    const float* W2       = (const float*)d_in[8];
    const float* b2       = (const float*)d_in[9];
    float* out = (float*)d_out;

    lstm_kernel<<<1024, 128>>>(x, Wih0, Wih_rest, Whh, bih, bhh);
    mlp1_kernel<<<dim3(32, NCHUNK), 256>>>(W1);
    mlp2_kernel<<<32, 256>>>(W2, b1, b2, out);
}

// round 13
// speedup vs baseline: 1.1780x; 1.1780x over previous
#include <cuda_runtime.h>
#include <cuda_bf16.h>

#define B_  8192
#define T_  200
#define IN_ 4
#define H_  16
#define L_  4
#define MLP_IN  (H_ * T_)   // 3200
#define MLP_HID 64
#define MLP_OUT 28
#define NCHUNK  16          // mlp1 K-chunks (200 rows each)

typedef unsigned long long ull;

// ---------------- scratch (no allocations allowed) ----------------
__device__ float g_h3[(long)MLP_IN * B_];                 // [m][b]
__device__ float g_partial[NCHUNK * MLP_HID * B_];        // [chunk][j][b]

// ---------------- packed f32x2 helpers ----------------
__device__ __forceinline__ ull pack2(float lo, float hi) {
    ull r; asm("mov.b64 %0, {%1, %2};" : "=l"(r) : "f"(lo), "f"(hi)); return r;
}
__device__ __forceinline__ void unpack2(ull v, float& lo, float& hi) {
    asm("mov.b64 {%0, %1}, %2;" : "=f"(lo), "=f"(hi) : "l"(v));
}
__device__ __forceinline__ ull ffma2(ull a, ull b, ull c) {
    ull d; asm("fma.rn.f32x2 %0, %1, %2, %3;" : "=l"(d) : "l"(a), "l"(b), "l"(c)); return d;
}

// ---------------- activations via MUFU.TANH (1 MUFU each) ------------
__device__ __forceinline__ float tanh_hw(float x) {
    float y; asm("tanh.approx.f32 %0, %1;" : "=f"(y) : "f"(x)); return y;
}
__device__ __forceinline__ float sigmoid_hw(float x) {
    return fmaf(tanh_hw(0.5f * x), 0.5f, 0.5f);
}

// h ring buffer: float hbuf[parity(2)][layer(4)][eg(8)][row 20 (16 used, pad 4)]
#define HB_ROW  20
#define HB_SLOT (8 * HB_ROW)          // one (parity, layer) slot
#define HB_PAR  (4 * HB_SLOT)
// x slot: float xslot[parity(2)][eg(8)][8 (4 used + pad)]
#define XB_ROW  8
#define XB_PAR  (8 * XB_ROW)
#define HB_TOTAL (2 * HB_PAR + 2 * XB_PAR)

// =====================================================================
// Layer-pipelined LSTM: CTA = 4 warps = 4 layers, 8 batch elems.
// Warp l (rotated by bid) holds layer-l weights in registers (f32x2
// k-pairs); computes t = i - l; one __syncthreads per iteration.
// x prefetched one step ahead into smem by the l==0 warp (hides LDG).
// 1024 CTAs x 128 threads, 2 CTAs/SM.
// =====================================================================
__global__ void __launch_bounds__(128, 2) lstm_kernel(
    const float* __restrict__ x,         // [B, T, IN]
    const float* __restrict__ Wih0,      // [64, 4]
    const float* __restrict__ Wih_rest,  // [3, 64, 16]
    const float* __restrict__ Whh,       // [4, 64, 16]
    const float* __restrict__ bih,       // [4, 64]
    const float* __restrict__ bhh)       // [4, 64]
{
    __shared__ __align__(16) float hbuf[HB_TOTAL];
    float* const xbuf = hbuf + 2 * HB_PAR;

    const int wid  = threadIdx.x >> 5;
    const int lane = threadIdx.x & 31;
    const int sub  = lane & 15;
    const int grp  = lane >> 4;
    const int l    = (wid + (int)blockIdx.x) & 3;        // layer rotation
    const int b0c  = (int)blockIdx.x * 8;                // CTA batch base
    const int b0   = b0c + grp * 4;                      // elems b0..b0+3

    for (int i = threadIdx.x; i < HB_TOTAL; i += blockDim.x) hbuf[i] = 0.0f;

    // ---- load this layer's weights into registers (k-pair packed) ----
    ull Wrec[4][8];   // [gate][kpair]
    ull Win[4][8];
    ull biasR[4];
#pragma unroll
    for (int g = 0; g < 4; ++g) {
        const float* rsrc = Whh + l * 1024 + (g * 16 + sub) * 16;
#pragma unroll
        for (int kc = 0; kc < 4; ++kc) {
            ulonglong2 v = *reinterpret_cast<const ulonglong2*>(rsrc + kc * 4);
            Wrec[g][2 * kc] = v.x; Wrec[g][2 * kc + 1] = v.y;
        }
        if (l == 0) {
            ulonglong2 v = *reinterpret_cast<const ulonglong2*>(Wih0 + (g * 16 + sub) * IN_);
            Win[g][0] = v.x; Win[g][1] = v.y;
#pragma unroll
            for (int kp = 2; kp < 8; ++kp) Win[g][kp] = 0ull;
        } else {
            const float* isrc = Wih_rest + (l - 1) * 1024 + (g * 16 + sub) * 16;
#pragma unroll
            for (int kc = 0; kc < 4; ++kc) {
                ulonglong2 v = *reinterpret_cast<const ulonglong2*>(isrc + kc * 4);
                Win[g][2 * kc] = v.x; Win[g][2 * kc + 1] = v.y;
            }
        }
        biasR[g] = pack2(bih[l * 64 + g * 16 + sub] + bhh[l * 64 + g * 16 + sub], 0.0f);
    }

    // initial x(0) into xbuf parity 1 (read at iter 0)
    if (threadIdx.x < 8) {
        float4 v = *reinterpret_cast<const float4*>(x + (long)(b0c + threadIdx.x) * (T_ * IN_));
        *reinterpret_cast<float4*>(xbuf + XB_PAR + threadIdx.x * XB_ROW) = v;
    }

    float c_own[4] = {0.0f, 0.0f, 0.0f, 0.0f};
    __syncthreads();

    for (int i = 0; i < T_ + L_ - 1; ++i) {
        const int p = i & 1;
        const int t = i - l;
        const bool active = ((unsigned)t < (unsigned)T_);

        if (active) {
            // l==0 warp prefetches x(t+1) for next iteration (hides LDG)
            if (l == 0 && lane < 8 && t + 1 < T_) {
                float4 v = *reinterpret_cast<const float4*>(
                    x + (long)(b0c + lane) * (T_ * IN_) + (t + 1) * IN_);
                *reinterpret_cast<float4*>(xbuf + p * XB_PAR + lane * XB_ROW) = v;
            }

            ull acc[4][4];   // [gate][e], halves = (even-k, odd-k) partials
#pragma unroll
            for (int g = 0; g < 4; ++g)
#pragma unroll
                for (int e = 0; e < 4; ++e) acc[g][e] = biasR[g];

            // ---- input projection ----
            if (l == 0) {
                const float* xsrc = xbuf + (1 - p) * XB_PAR;
#pragma unroll
                for (int e = 0; e < 4; ++e) {
                    ulonglong2 xv = *reinterpret_cast<const ulonglong2*>(
                        xsrc + (grp * 4 + e) * XB_ROW);
#pragma unroll
                    for (int g = 0; g < 4; ++g) {
                        acc[g][e] = ffma2(Win[g][0], xv.x, acc[g][e]);
                        acc[g][e] = ffma2(Win[g][1], xv.y, acc[g][e]);
                    }
                }
            } else {
                const float* hsrc = hbuf + (1 - p) * HB_PAR + (l - 1) * HB_SLOT;
#pragma unroll
                for (int kc = 0; kc < 4; ++kc) {
                    ulonglong2 hv[4];
#pragma unroll
                    for (int e = 0; e < 4; ++e)
                        hv[e] = *reinterpret_cast<const ulonglong2*>(
                            hsrc + (grp * 4 + e) * HB_ROW + kc * 4);
#pragma unroll
                    for (int g = 0; g < 4; ++g)
#pragma unroll
                        for (int e = 0; e < 4; ++e) {
                            acc[g][e] = ffma2(Win[g][2 * kc],     hv[e].x, acc[g][e]);
                            acc[g][e] = ffma2(Win[g][2 * kc + 1], hv[e].y, acc[g][e]);
                        }
                }
            }

            // ---- recurrent projection (own layer's h at t-1) ----
            {
                const float* hsrc = hbuf + (1 - p) * HB_PAR + l * HB_SLOT;
#pragma unroll
                for (int kc = 0; kc < 4; ++kc) {
                    ulonglong2 hv[4];
#pragma unroll
                    for (int e = 0; e < 4; ++e)
                        hv[e] = *reinterpret_cast<const ulonglong2*>(
                            hsrc + (grp * 4 + e) * HB_ROW + kc * 4);
#pragma unroll
                    for (int g = 0; g < 4; ++g)
#pragma unroll
                        for (int e = 0; e < 4; ++e) {
                            acc[g][e] = ffma2(Wrec[g][2 * kc],     hv[e].x, acc[g][e]);
                            acc[g][e] = ffma2(Wrec[g][2 * kc + 1], hv[e].y, acc[g][e]);
                        }
                }
            }

            // ---- horizontal add + activations (MUFU.TANH) + state ----
            float hn[4];
#pragma unroll
            for (int e = 0; e < 4; ++e) {
                float lo, hi, ai, af, ag, ao;
                unpack2(acc[0][e], lo, hi); ai = lo + hi;
                unpack2(acc[1][e], lo, hi); af = lo + hi;
                unpack2(acc[2][e], lo, hi); ag = lo + hi;
                unpack2(acc[3][e], lo, hi); ao = lo + hi;
                float iv = sigmoid_hw(ai);
                float fv = sigmoid_hw(af);
                float gv = tanh_hw(ag);
                float ov = sigmoid_hw(ao);
                float cv = fmaf(fv, c_own[e], iv * gv);
                c_own[e] = cv;
                hn[e] = ov * tanh_hw(cv);
            }

            // ---- publish new h into buf[p] slot l ----
            {
                float* hdst = hbuf + p * HB_PAR + l * HB_SLOT;
#pragma unroll
                for (int e = 0; e < 4; ++e)
                    hdst[(grp * 4 + e) * HB_ROW + sub] = hn[e];
            }
            if (l == L_ - 1) {
                float4 v = make_float4(hn[0], hn[1], hn[2], hn[3]);
                *reinterpret_cast<float4*>(g_h3 + (long)(t * 16 + sub) * B_ + b0) = v;
            }
        }
        __syncthreads();
    }
}

// =====================================================================
// MLP phase 1: partial hid sums over NCHUNK chunks of 200 rows.
// =====================================================================
__global__ void __launch_bounds__(256) mlp1_kernel(const float* __restrict__ W1)
{
    __shared__ float4 W1s[200 * 16];   // [mm][j4], 51.2 KB
    const int chunk = blockIdx.y;
    const int m0 = chunk * 200;
    {
        float* w = reinterpret_cast<float*>(W1s);
        for (int idx = threadIdx.x; idx < 200 * MLP_HID; idx += blockDim.x) {
            int mm = idx >> 6, j = idx & 63;
            w[idx] = W1[j * MLP_IN + m0 + mm];
        }
    }
    __syncthreads();

    const int jq = threadIdx.x & 3;
    const int bq = threadIdx.x >> 2;
    const int b0 = blockIdx.x * 256 + bq * 4;

    ull acc[8][4];
#pragma unroll
    for (int jp = 0; jp < 8; ++jp)
#pragma unroll
        for (int e = 0; e < 4; ++e) acc[jp][e] = 0ull;

    for (int mm = 0; mm < 200; ++mm) {
        float4 f = *reinterpret_cast<const float4*>(g_h3 + (long)(m0 + mm) * B_ + b0);
        ull f2[4] = { pack2(f.x, f.x), pack2(f.y, f.y), pack2(f.z, f.z), pack2(f.w, f.w) };
#pragma unroll
        for (int j4 = 0; j4 < 4; ++j4) {
            ulonglong2 wp = *reinterpret_cast<const ulonglong2*>(&W1s[mm * 16 + jq * 4 + j4]);
#pragma unroll
            for (int e = 0; e < 4; ++e) {
                acc[j4 * 2 + 0][e] = ffma2(wp.x, f2[e], acc[j4 * 2 + 0][e]);
                acc[j4 * 2 + 1][e] = ffma2(wp.y, f2[e], acc[j4 * 2 + 1][e]);
            }
        }
    }
#pragma unroll
    for (int jp = 0; jp < 8; ++jp) {
        float v0[4], v1[4];
#pragma unroll
        for (int e = 0; e < 4; ++e) unpack2(acc[jp][e], v0[e], v1[e]);
        int j = jq * 16 + jp * 2;
        *reinterpret_cast<float4*>(g_partial + ((long)chunk * MLP_HID + j) * B_ + b0) =
            make_float4(v0[0], v0[1], v0[2], v0[3]);
        *reinterpret_cast<float4*>(g_partial + ((long)chunk * MLP_HID + j + 1) * B_ + b0) =
            make_float4(v1[0], v1[1], v1[2], v1[3]);
    }
}

// =====================================================================
// MLP phase 2: reduce chunks, bias+relu, W2, write out [B, 28].
// =====================================================================
__global__ void __launch_bounds__(256) mlp2_kernel(
    const float* __restrict__ W2,   // [28, 64]
    const float* __restrict__ b1,   // [64]
    const float* __restrict__ b2,   // [28]
    float* __restrict__ out)        // [B, 28]
{
    __shared__ float W2s[MLP_OUT * MLP_HID];
    __shared__ float b1s[MLP_HID];
    __shared__ float b2s[MLP_OUT];
    for (int idx = threadIdx.x; idx < MLP_OUT * MLP_HID; idx += blockDim.x)
        W2s[idx] = W2[idx];
    if (threadIdx.x < MLP_HID) b1s[threadIdx.x] = b1[threadIdx.x];
    if (threadIdx.x < MLP_OUT) b2s[threadIdx.x] = b2[threadIdx.x];
    __syncthreads();

    const int b = blockIdx.x * 256 + threadIdx.x;
    float hid[MLP_HID];
#pragma unroll
    for (int j = 0; j < MLP_HID; ++j) hid[j] = b1s[j];

    for (int ch = 0; ch < NCHUNK; ++ch) {
#pragma unroll
        for (int j = 0; j < MLP_HID; ++j)
            hid[j] += g_partial[((long)ch * MLP_HID + j) * B_ + b];
    }
#pragma unroll
    for (int j = 0; j < MLP_HID; ++j) hid[j] = fmaxf(hid[j], 0.0f);

#pragma unroll
    for (int o = 0; o < MLP_OUT; ++o) {
        float a = b2s[o];
#pragma unroll
        for (int j = 0; j < MLP_HID; ++j)
            a = fmaf(hid[j], W2s[o * MLP_HID + j], a);
        out[(long)b * MLP_OUT + o] = a;
    }
}

// =====================================================================
extern "C" void kernel_launch(void* const* d_in, const int* in_sizes, int n_in,
                              void* d_out, int out_size)
{
    const float* x        = (const float*)d_in[0];
    const float* Wih0     = (const float*)d_in[1];
    const float* Wih_rest = (const float*)d_in[2];
    const float* Whh      = (const float*)d_in[3];
    const float* bih      = (const float*)d_in[4];
    const float* bhh      = (const float*)d_in[5];
    const float* W1       = (const float*)d_in[6];
    const float* b1       = (const float*)d_in[7];
    const float* W2       = (const float*)d_in[8];
    const float* b2       = (const float*)d_in[9];
    float* out = (float*)d_out;

    lstm_kernel<<<1024, 128>>>(x, Wih0, Wih_rest, Whh, bih, bhh);
    mlp1_kernel<<<dim3(32, NCHUNK), 256>>>(W1);
    mlp2_kernel<<<32, 256>>>(W2, b1, b2, out);
}

// round 14
// speedup vs baseline: 1.1822x; 1.0035x over previous
#include <cuda_runtime.h>
#include <cuda_bf16.h>

#define B_  8192
#define T_  200
#define IN_ 4
#define H_  16
#define L_  4
#define MLP_IN  (H_ * T_)   // 3200
#define MLP_HID 64
#define MLP_OUT 28
#define NCHUNK  16          // mlp1 K-chunks (200 rows each)

typedef unsigned long long ull;

// ---------------- scratch (no allocations allowed) ----------------
__device__ float g_h3[(long)MLP_IN * B_];                 // [m][b]
__device__ float g_partial[NCHUNK * MLP_HID * B_];        // [chunk][j][b]

// ---------------- packed f32x2 helpers ----------------
__device__ __forceinline__ ull pack2(float lo, float hi) {
    ull r; asm("mov.b64 %0, {%1, %2};" : "=l"(r) : "f"(lo), "f"(hi)); return r;
}
__device__ __forceinline__ void unpack2(ull v, float& lo, float& hi) {
    asm("mov.b64 {%0, %1}, %2;" : "=f"(lo), "=f"(hi) : "l"(v));
}
__device__ __forceinline__ ull ffma2(ull a, ull b, ull c) {
    ull d; asm("fma.rn.f32x2 %0, %1, %2, %3;" : "=l"(d) : "l"(a), "l"(b), "l"(c)); return d;
}

// ---------------- activations via MUFU.TANH (1 MUFU each) ------------
__device__ __forceinline__ float tanh_hw(float x) {
    float y; asm("tanh.approx.f32 %0, %1;" : "=f"(y) : "f"(x)); return y;
}
__device__ __forceinline__ float sigmoid_hw(float x) {
    return fmaf(tanh_hw(0.5f * x), 0.5f, 0.5f);
}

// h ring buffer: float hbuf[parity(2)][layer(4)][eg(8)][row 20 (16 used, pad 4)]
#define HB_ROW  20
#define HB_SLOT (8 * HB_ROW)          // one (parity, layer) slot
#define HB_PAR  (4 * HB_SLOT)
// x slot: float xslot[parity(2)][eg(8)][8 (4 used + pad)]
#define XB_ROW  8
#define XB_PAR  (8 * XB_ROW)
#define HB_TOTAL (2 * HB_PAR + 2 * XB_PAR)

// Win in smem: ull WinS[((l*4+g)*8+kp)*16 + j] = pack(W[k=2kp], W[k=2kp+1])
#define WINS_TOTAL (L_ * 4 * 8 * 16)   // 2048 ull = 16 KB

// =====================================================================
// Layer-pipelined LSTM: CTA = 4 warps = 4 layers, 8 batch elems.
// Warp l (rotated by bid) holds layer-l RECURRENT weights in registers;
// input-projection weights live in smem (1-wf broadcast loads) to cut
// registers below 170 -> 3 CTAs/SM (12 warps).
// One __syncthreads per iteration; x prefetched a step ahead by warp 0.
// 1024 CTAs x 128 threads.
// =====================================================================
__global__ void __launch_bounds__(128, 3) lstm_kernel(
    const float* __restrict__ x,         // [B, T, IN]
    const float* __restrict__ Wih0,      // [64, 4]
    const float* __restrict__ Wih_rest,  // [3, 64, 16]
    const float* __restrict__ Whh,       // [4, 64, 16]
    const float* __restrict__ bih,       // [4, 64]
    const float* __restrict__ bhh)       // [4, 64]
{
    __shared__ __align__(16) float hbuf[HB_TOTAL];
    __shared__ __align__(16) ull  WinS[WINS_TOTAL];
    float* const xbuf = hbuf + 2 * HB_PAR;

    const int wid  = threadIdx.x >> 5;
    const int lane = threadIdx.x & 31;
    const int sub  = lane & 15;
    const int grp  = lane >> 4;
    const int l    = (wid + (int)blockIdx.x) & 3;        // layer rotation
    const int b0c  = (int)blockIdx.x * 8;                // CTA batch base
    const int b0   = b0c + grp * 4;                      // elems b0..b0+3

    for (int i = threadIdx.x; i < HB_TOTAL; i += blockDim.x) hbuf[i] = 0.0f;

    // ---- stage Win into smem: [(l*4+g)*8+kp][j] k-pair packed ----
    for (int idx = threadIdx.x; idx < WINS_TOTAL; idx += blockDim.x) {
        int j  = idx & 15;
        int kp = (idx >> 4) & 7;
        int g  = (idx >> 7) & 3;
        int li = idx >> 9;
        ull v;
        if (li == 0) {
            if (kp < 2)
                v = *reinterpret_cast<const ull*>(Wih0 + (g * 16 + j) * IN_ + kp * 2);
            else
                v = 0ull;
        } else {
            v = *reinterpret_cast<const ull*>(
                Wih_rest + (li - 1) * 1024 + (g * 16 + j) * 16 + kp * 2);
        }
        WinS[idx] = v;
    }

    // ---- this layer's recurrent weights + bias into registers ----
    ull Wrec[4][8];   // [gate][kpair]
    ull biasR[4];
#pragma unroll
    for (int g = 0; g < 4; ++g) {
        const float* rsrc = Whh + l * 1024 + (g * 16 + sub) * 16;
#pragma unroll
        for (int kc = 0; kc < 4; ++kc) {
            ulonglong2 v = *reinterpret_cast<const ulonglong2*>(rsrc + kc * 4);
            Wrec[g][2 * kc] = v.x; Wrec[g][2 * kc + 1] = v.y;
        }
        biasR[g] = pack2(bih[l * 64 + g * 16 + sub] + bhh[l * 64 + g * 16 + sub], 0.0f);
    }

    // initial x(0) into xbuf parity 1 (read at iter 0)
    if (threadIdx.x < 8) {
        float4 v = *reinterpret_cast<const float4*>(x + (long)(b0c + threadIdx.x) * (T_ * IN_));
        *reinterpret_cast<float4*>(xbuf + XB_PAR + threadIdx.x * XB_ROW) = v;
    }

    float c_own[4] = {0.0f, 0.0f, 0.0f, 0.0f};
    const ull* const winL = WinS + (l * 4) * 8 * 16;   // [g][kp][j]
    __syncthreads();

    for (int i = 0; i < T_ + L_ - 1; ++i) {
        const int p = i & 1;
        const int t = i - l;
        const bool active = ((unsigned)t < (unsigned)T_);

        if (active) {
            // l==0 warp prefetches x(t+1) for next iteration (hides LDG)
            if (l == 0 && lane < 8 && t + 1 < T_) {
                float4 v = *reinterpret_cast<const float4*>(
                    x + (long)(b0c + lane) * (T_ * IN_) + (t + 1) * IN_);
                *reinterpret_cast<float4*>(xbuf + p * XB_PAR + lane * XB_ROW) = v;
            }

            ull acc[4][4];   // [gate][e], halves = (even-k, odd-k) partials
#pragma unroll
            for (int g = 0; g < 4; ++g)
#pragma unroll
                for (int e = 0; e < 4; ++e) acc[g][e] = biasR[g];

            // ---- input projection (weights from smem) ----
            if (l == 0) {
                const float* xsrc = xbuf + (1 - p) * XB_PAR;
#pragma unroll
                for (int e = 0; e < 4; ++e) {
                    ulonglong2 xv = *reinterpret_cast<const ulonglong2*>(
                        xsrc + (grp * 4 + e) * XB_ROW);
#pragma unroll
                    for (int g = 0; g < 4; ++g) {
                        ull w0 = winL[(g * 8 + 0) * 16 + sub];
                        ull w1 = winL[(g * 8 + 1) * 16 + sub];
#pragma unroll
                        for (int ee = 0; ee < 1; ++ee) {}  // keep shape
                        acc[g][e] = ffma2(w0, xv.x, acc[g][e]);
                        acc[g][e] = ffma2(w1, xv.y, acc[g][e]);
                    }
                }
            } else {
                const float* hsrc = hbuf + (1 - p) * HB_PAR + (l - 1) * HB_SLOT;
#pragma unroll
                for (int kc = 0; kc < 4; ++kc) {
                    ulonglong2 hv[4];
#pragma unroll
                    for (int e = 0; e < 4; ++e)
                        hv[e] = *reinterpret_cast<const ulonglong2*>(
                            hsrc + (grp * 4 + e) * HB_ROW + kc * 4);
#pragma unroll
                    for (int g = 0; g < 4; ++g) {
                        ull w0 = winL[(g * 8 + 2 * kc + 0) * 16 + sub];
                        ull w1 = winL[(g * 8 + 2 * kc + 1) * 16 + sub];
#pragma unroll
                        for (int e = 0; e < 4; ++e) {
                            acc[g][e] = ffma2(w0, hv[e].x, acc[g][e]);
                            acc[g][e] = ffma2(w1, hv[e].y, acc[g][e]);
                        }
                    }
                }
            }

            // ---- recurrent projection (register weights) ----
            {
                const float* hsrc = hbuf + (1 - p) * HB_PAR + l * HB_SLOT;
#pragma unroll
                for (int kc = 0; kc < 4; ++kc) {
                    ulonglong2 hv[4];
#pragma unroll
                    for (int e = 0; e < 4; ++e)
                        hv[e] = *reinterpret_cast<const ulonglong2*>(
                            hsrc + (grp * 4 + e) * HB_ROW + kc * 4);
#pragma unroll
                    for (int g = 0; g < 4; ++g)
#pragma unroll
                        for (int e = 0; e < 4; ++e) {
                            acc[g][e] = ffma2(Wrec[g][2 * kc],     hv[e].x, acc[g][e]);
                            acc[g][e] = ffma2(Wrec[g][2 * kc + 1], hv[e].y, acc[g][e]);
                        }
                }
            }

            // ---- horizontal add + activations (MUFU.TANH) + state ----
            float hn[4];
#pragma unroll
            for (int e = 0; e < 4; ++e) {
                float lo, hi, ai, af, ag, ao;
                unpack2(acc[0][e], lo, hi); ai = lo + hi;
                unpack2(acc[1][e], lo, hi); af = lo + hi;
                unpack2(acc[2][e], lo, hi); ag = lo + hi;
                unpack2(acc[3][e], lo, hi); ao = lo + hi;
                float iv = sigmoid_hw(ai);
                float fv = sigmoid_hw(af);
                float gv = tanh_hw(ag);
                float ov = sigmoid_hw(ao);
                float cv = fmaf(fv, c_own[e], iv * gv);
                c_own[e] = cv;
                hn[e] = ov * tanh_hw(cv);
            }

            // ---- publish new h into buf[p] slot l ----
            {
                float* hdst = hbuf + p * HB_PAR + l * HB_SLOT;
#pragma unroll
                for (int e = 0; e < 4; ++e)
                    hdst[(grp * 4 + e) * HB_ROW + sub] = hn[e];
            }
            if (l == L_ - 1) {
                float4 v = make_float4(hn[0], hn[1], hn[2], hn[3]);
                *reinterpret_cast<float4*>(g_h3 + (long)(t * 16 + sub) * B_ + b0) = v;
            }
        }
        __syncthreads();
    }
}

// =====================================================================
// MLP phase 1: partial hid sums over NCHUNK chunks of 200 rows.
// =====================================================================
__global__ void __launch_bounds__(256) mlp1_kernel(const float* __restrict__ W1)
{
    __shared__ float4 W1s[200 * 16];   // [mm][j4], 51.2 KB
    const int chunk = blockIdx.y;
    const int m0 = chunk * 200;
    {
        float* w = reinterpret_cast<float*>(W1s);
        for (int idx = threadIdx.x; idx < 200 * MLP_HID; idx += blockDim.x) {
            int mm = idx >> 6, j = idx & 63;
            w[idx] = W1[j * MLP_IN + m0 + mm];
        }
    }
    __syncthreads();

    const int jq = threadIdx.x & 3;
    const int bq = threadIdx.x >> 2;
    const int b0 = blockIdx.x * 256 + bq * 4;

    ull acc[8][4];
#pragma unroll
    for (int jp = 0; jp < 8; ++jp)
#pragma unroll
        for (int e = 0; e < 4; ++e) acc[jp][e] = 0ull;

    for (int mm = 0; mm < 200; ++mm) {
        float4 f = *reinterpret_cast<const float4*>(g_h3 + (long)(m0 + mm) * B_ + b0);
        ull f2[4] = { pack2(f.x, f.x), pack2(f.y, f.y), pack2(f.z, f.z), pack2(f.w, f.w) };
#pragma unroll
        for (int j4 = 0; j4 < 4; ++j4) {
            ulonglong2 wp = *reinterpret_cast<const ulonglong2*>(&W1s[mm * 16 + jq * 4 + j4]);
#pragma unroll
            for (int e = 0; e < 4; ++e) {
                acc[j4 * 2 + 0][e] = ffma2(wp.x, f2[e], acc[j4 * 2 + 0][e]);
                acc[j4 * 2 + 1][e] = ffma2(wp.y, f2[e], acc[j4 * 2 + 1][e]);
            }
        }
    }
#pragma unroll
    for (int jp = 0; jp < 8; ++jp) {
        float v0[4], v1[4];
#pragma unroll
        for (int e = 0; e < 4; ++e) unpack2(acc[jp][e], v0[e], v1[e]);
        int j = jq * 16 + jp * 2;
        *reinterpret_cast<float4*>(g_partial + ((long)chunk * MLP_HID + j) * B_ + b0) =
            make_float4(v0[0], v0[1], v0[2], v0[3]);
        *reinterpret_cast<float4*>(g_partial + ((long)chunk * MLP_HID + j + 1) * B_ + b0) =
            make_float4(v1[0], v1[1], v1[2], v1[3]);
    }
}

// =====================================================================
// MLP phase 2: reduce chunks, bias+relu, W2, write out [B, 28].
// =====================================================================
__global__ void __launch_bounds__(256) mlp2_kernel(
    const float* __restrict__ W2,   // [28, 64]
    const float* __restrict__ b1,   // [64]
    const float* __restrict__ b2,   // [28]
    float* __restrict__ out)        // [B, 28]
{
    __shared__ float W2s[MLP_OUT * MLP_HID];
    __shared__ float b1s[MLP_HID];
    __shared__ float b2s[MLP_OUT];
    for (int idx = threadIdx.x; idx < MLP_OUT * MLP_HID; idx += blockDim.x)
        W2s[idx] = W2[idx];
    if (threadIdx.x < MLP_HID) b1s[threadIdx.x] = b1[threadIdx.x];
    if (threadIdx.x < MLP_OUT) b2s[threadIdx.x] = b2[threadIdx.x];
    __syncthreads();

    const int b = blockIdx.x * 256 + threadIdx.x;
    float hid[MLP_HID];
#pragma unroll
    for (int j = 0; j < MLP_HID; ++j) hid[j] = b1s[j];

    for (int ch = 0; ch < NCHUNK; ++ch) {
#pragma unroll
        for (int j = 0; j < MLP_HID; ++j)
            hid[j] += g_partial[((long)ch * MLP_HID + j) * B_ + b];
    }
#pragma unroll
    for (int j = 0; j < MLP_HID; ++j) hid[j] = fmaxf(hid[j], 0.0f);

#pragma unroll
    for (int o = 0; o < MLP_OUT; ++o) {
        float a = b2s[o];
#pragma unroll
        for (int j = 0; j < MLP_HID; ++j)
            a = fmaf(hid[j], W2s[o * MLP_HID + j], a);
        out[(long)b * MLP_OUT + o] = a;
    }
}

// =====================================================================
extern "C" void kernel_launch(void* const* d_in, const int* in_sizes, int n_in,
                              void* d_out, int out_size)
{
    const float* x        = (const float*)d_in[0];
    const float* Wih0     = (const float*)d_in[1];
    const float* Wih_rest = (const float*)d_in[2];
    const float* Whh      = (const float*)d_in[3];
    const float* bih      = (const float*)d_in[4];
    const float* bhh      = (const float*)d_in[5];
    const float* W1       = (const float*)d_in[6];
    const float* b1       = (const float*)d_in[7];
    const float* W2       = (const float*)d_in[8];
    const float* b2       = (const float*)d_in[9];
    float* out = (float*)d_out;

    lstm_kernel<<<1024, 128>>>(x, Wih0, Wih_rest, Whh, bih, bhh);
    mlp1_kernel<<<dim3(32, NCHUNK), 256>>>(W1);
    mlp2_kernel<<<32, 256>>>(W2, b1, b2, out);
}

// round 15
// speedup vs baseline: 1.2261x; 1.0371x over previous
#include <cuda_runtime.h>
#include <cuda_bf16.h>

#define B_  8192
#define T_  200
#define IN_ 4
#define H_  16
#define L_  4
#define MLP_IN  (H_ * T_)   // 3200
#define MLP_HID 64
#define MLP_OUT 28
#define NCHUNK  16          // mlp1 K-chunks (200 rows each)

typedef unsigned long long ull;

// ---------------- scratch (no allocations allowed) ----------------
__device__ float g_h3[(long)MLP_IN * B_];                 // [m][b]
__device__ float g_partial[NCHUNK * MLP_HID * B_];        // [chunk][j][b]

// ---------------- packed f32x2 helpers ----------------
__device__ __forceinline__ ull pack2(float lo, float hi) {
    ull r; asm("mov.b64 %0, {%1, %2};" : "=l"(r) : "f"(lo), "f"(hi)); return r;
}
__device__ __forceinline__ void unpack2(ull v, float& lo, float& hi) {
    asm("mov.b64 {%0, %1}, %2;" : "=f"(lo), "=f"(hi) : "l"(v));
}
__device__ __forceinline__ ull ffma2(ull a, ull b, ull c) {
    ull d; asm("fma.rn.f32x2 %0, %1, %2, %3;" : "=l"(d) : "l"(a), "l"(b), "l"(c)); return d;
}

// ---------------- activations via MUFU.TANH (1 MUFU each) ------------
__device__ __forceinline__ float tanh_hw(float x) {
    float y; asm("tanh.approx.f32 %0, %1;" : "=f"(y) : "f"(x)); return y;
}
__device__ __forceinline__ float sigmoid_hw(float x) {
    return fmaf(tanh_hw(0.5f * x), 0.5f, 0.5f);
}

// h ring buffer: float hbuf[parity(2)][layer(4)][eg(8)][row 20 (16 used, pad 4)]
#define HB_ROW  20
#define HB_SLOT (8 * HB_ROW)
#define HB_PAR  (4 * HB_SLOT)
// x slot: float xslot[parity(2)][eg(8)][8 (4 used + pad)]
#define XB_ROW  8
#define XB_PAR  (8 * XB_ROW)
#define HB_TOTAL (2 * HB_PAR + 2 * XB_PAR)

// paired weight layouts (ulonglong2 = 4 consecutive k as two f32x2 pairs):
//   WinP [((l*4+g)*4+kc)*16 + j]  : input-projection, all gates   (16 KB)
//   WrecP[((l*2+gp)*4+kc)*16 + j] : recurrent, gates 2..3 only    (8 KB)
//   biasP2[(l*2+gp)*16 + j]       : (bias_g, 0) pairs, g = 2gp,2gp+1 (2 KB)
#define WINP_N  (L_ * 4 * 4 * 16)
#define WRECP_N (L_ * 2 * 4 * 16)
#define BIASP_N (L_ * 2 * 16)

// =====================================================================
// Layer-pipelined LSTM: CTA = 4 warps = 4 layers, 8 batch elems.
// Warp l keeps gates 0..1 recurrent weights in registers; gates 2..3
// recurrent + all input-projection weights + bias live in smem with
// paired LDS.128 layout. regs <= 128 -> 4 CTAs/SM (16 warps).
// One __syncthreads per iteration; x prefetched a step ahead by warp 0.
// 1024 CTAs x 128 threads.
// =====================================================================
__global__ void __launch_bounds__(128, 4) lstm_kernel(
    const float* __restrict__ x,         // [B, T, IN]
    const float* __restrict__ Wih0,      // [64, 4]
    const float* __restrict__ Wih_rest,  // [3, 64, 16]
    const float* __restrict__ Whh,       // [4, 64, 16]
    const float* __restrict__ bih,       // [4, 64]
    const float* __restrict__ bhh)       // [4, 64]
{
    __shared__ __align__(16) float hbuf[HB_TOTAL];
    __shared__ __align__(16) ulonglong2 WinP[WINP_N];
    __shared__ __align__(16) ulonglong2 WrecP[WRECP_N];
    __shared__ __align__(16) ulonglong2 biasP2[BIASP_N];
    float* const xbuf = hbuf + 2 * HB_PAR;

    const int wid  = threadIdx.x >> 5;
    const int lane = threadIdx.x & 31;
    const int sub  = lane & 15;
    const int grp  = lane >> 4;
    const int l    = (wid + (int)blockIdx.x) & 3;        // layer rotation
    const int b0c  = (int)blockIdx.x * 8;                // CTA batch base
    const int b0   = b0c + grp * 4;                      // elems b0..b0+3

    for (int i = threadIdx.x; i < HB_TOTAL; i += blockDim.x) hbuf[i] = 0.0f;

    // ---- stage WinP: float4 chunks of Wih rows ----
    for (int idx = threadIdx.x; idx < WINP_N; idx += blockDim.x) {
        int j  = idx & 15;
        int kc = (idx >> 4) & 3;
        int g  = (idx >> 6) & 3;
        int li = idx >> 8;
        float4 v = make_float4(0.f, 0.f, 0.f, 0.f);
        if (li == 0) {
            if (kc == 0) v = *reinterpret_cast<const float4*>(Wih0 + (g * 16 + j) * IN_);
        } else {
            v = *reinterpret_cast<const float4*>(
                Wih_rest + (li - 1) * 1024 + (g * 16 + j) * 16 + kc * 4);
        }
        WinP[idx] = *reinterpret_cast<ulonglong2*>(&v);
    }
    // ---- stage WrecP (gates 2..3) ----
    for (int idx = threadIdx.x; idx < WRECP_N; idx += blockDim.x) {
        int j  = idx & 15;
        int kc = (idx >> 4) & 3;
        int gp = (idx >> 6) & 1;
        int li = idx >> 7;
        float4 v = *reinterpret_cast<const float4*>(
            Whh + li * 1024 + ((gp + 2) * 16 + j) * 16 + kc * 4);
        WrecP[idx] = *reinterpret_cast<ulonglong2*>(&v);
    }
    // ---- stage biasP2 ----
    for (int idx = threadIdx.x; idx < BIASP_N; idx += blockDim.x) {
        int j  = idx & 15;
        int gp = (idx >> 4) & 1;
        int li = idx >> 5;
        ulonglong2 v;
        v.x = pack2(bih[li * 64 + (2 * gp + 0) * 16 + j] + bhh[li * 64 + (2 * gp + 0) * 16 + j], 0.0f);
        v.y = pack2(bih[li * 64 + (2 * gp + 1) * 16 + j] + bhh[li * 64 + (2 * gp + 1) * 16 + j], 0.0f);
        biasP2[idx] = v;
    }

    // ---- gates 0..1 recurrent weights into registers ----
    ull Wrec[2][8];   // [gate][kpair]
#pragma unroll
    for (int g = 0; g < 2; ++g) {
        const float* rsrc = Whh + l * 1024 + (g * 16 + sub) * 16;
#pragma unroll
        for (int kc = 0; kc < 4; ++kc) {
            ulonglong2 v = *reinterpret_cast<const ulonglong2*>(rsrc + kc * 4);
            Wrec[g][2 * kc] = v.x; Wrec[g][2 * kc + 1] = v.y;
        }
    }

    // initial x(0) into xbuf parity 1 (read at iter 0)
    if (threadIdx.x < 8) {
        float4 v = *reinterpret_cast<const float4*>(x + (long)(b0c + threadIdx.x) * (T_ * IN_));
        *reinterpret_cast<float4*>(xbuf + XB_PAR + threadIdx.x * XB_ROW) = v;
    }

    float c_own[4] = {0.0f, 0.0f, 0.0f, 0.0f};
    const ulonglong2* const winL  = WinP  + (l * 4) * 4 * 16;  // [g][kc][j]
    const ulonglong2* const wrecL = WrecP + (l * 2) * 4 * 16;  // [gp][kc][j]
    const ulonglong2* const biasL = biasP2 + (l * 2) * 16;     // [gp][j]
    __syncthreads();

    for (int i = 0; i < T_ + L_ - 1; ++i) {
        const int p = i & 1;
        const int t = i - l;
        const bool active = ((unsigned)t < (unsigned)T_);

        if (active) {
            // l==0 warp prefetches x(t+1) for next iteration (hides LDG)
            if (l == 0 && lane < 8 && t + 1 < T_) {
                float4 v = *reinterpret_cast<const float4*>(
                    x + (long)(b0c + lane) * (T_ * IN_) + (t + 1) * IN_);
                *reinterpret_cast<float4*>(xbuf + p * XB_PAR + lane * XB_ROW) = v;
            }

            ull acc[4][4];   // [gate][e], halves = (even-k, odd-k) partials
            {
                ulonglong2 b01 = biasL[0 * 16 + sub];
                ulonglong2 b23 = biasL[1 * 16 + sub];
#pragma unroll
                for (int e = 0; e < 4; ++e) {
                    acc[0][e] = b01.x; acc[1][e] = b01.y;
                    acc[2][e] = b23.x; acc[3][e] = b23.y;
                }
            }

            // ---- input projection (paired smem weights) ----
            if (l == 0) {
                const float* xsrc = xbuf + (1 - p) * XB_PAR;
#pragma unroll
                for (int e = 0; e < 4; ++e) {
                    ulonglong2 xv = *reinterpret_cast<const ulonglong2*>(
                        xsrc + (grp * 4 + e) * XB_ROW);
#pragma unroll
                    for (int g = 0; g < 4; ++g) {
                        ulonglong2 wv = winL[(g * 4 + 0) * 16 + sub];
                        acc[g][e] = ffma2(wv.x, xv.x, acc[g][e]);
                        acc[g][e] = ffma2(wv.y, xv.y, acc[g][e]);
                    }
                }
            } else {
                const float* hsrc = hbuf + (1 - p) * HB_PAR + (l - 1) * HB_SLOT;
#pragma unroll
                for (int kc = 0; kc < 4; ++kc) {
                    ulonglong2 hv[4];
#pragma unroll
                    for (int e = 0; e < 4; ++e)
                        hv[e] = *reinterpret_cast<const ulonglong2*>(
                            hsrc + (grp * 4 + e) * HB_ROW + kc * 4);
#pragma unroll
                    for (int g = 0; g < 4; ++g) {
                        ulonglong2 wv = winL[(g * 4 + kc) * 16 + sub];
#pragma unroll
                        for (int e = 0; e < 4; ++e) {
                            acc[g][e] = ffma2(wv.x, hv[e].x, acc[g][e]);
                            acc[g][e] = ffma2(wv.y, hv[e].y, acc[g][e]);
                        }
                    }
                }
            }

            // ---- recurrent projection ----
            {
                const float* hsrc = hbuf + (1 - p) * HB_PAR + l * HB_SLOT;
#pragma unroll
                for (int kc = 0; kc < 4; ++kc) {
                    ulonglong2 hv[4];
#pragma unroll
                    for (int e = 0; e < 4; ++e)
                        hv[e] = *reinterpret_cast<const ulonglong2*>(
                            hsrc + (grp * 4 + e) * HB_ROW + kc * 4);
                    // gates 0..1 from registers
#pragma unroll
                    for (int g = 0; g < 2; ++g)
#pragma unroll
                        for (int e = 0; e < 4; ++e) {
                            acc[g][e] = ffma2(Wrec[g][2 * kc],     hv[e].x, acc[g][e]);
                            acc[g][e] = ffma2(Wrec[g][2 * kc + 1], hv[e].y, acc[g][e]);
                        }
                    // gates 2..3 from paired smem
#pragma unroll
                    for (int gp = 0; gp < 2; ++gp) {
                        ulonglong2 wv = wrecL[(gp * 4 + kc) * 16 + sub];
#pragma unroll
                        for (int e = 0; e < 4; ++e) {
                            acc[gp + 2][e] = ffma2(wv.x, hv[e].x, acc[gp + 2][e]);
                            acc[gp + 2][e] = ffma2(wv.y, hv[e].y, acc[gp + 2][e]);
                        }
                    }
                }
            }

            // ---- horizontal add + activations (MUFU.TANH) + state ----
            float hn[4];
#pragma unroll
            for (int e = 0; e < 4; ++e) {
                float lo, hi, ai, af, ag, ao;
                unpack2(acc[0][e], lo, hi); ai = lo + hi;
                unpack2(acc[1][e], lo, hi); af = lo + hi;
                unpack2(acc[2][e], lo, hi); ag = lo + hi;
                unpack2(acc[3][e], lo, hi); ao = lo + hi;
                float iv = sigmoid_hw(ai);
                float fv = sigmoid_hw(af);
                float gv = tanh_hw(ag);
                float ov = sigmoid_hw(ao);
                float cv = fmaf(fv, c_own[e], iv * gv);
                c_own[e] = cv;
                hn[e] = ov * tanh_hw(cv);
            }

            // ---- publish new h into buf[p] slot l ----
            {
                float* hdst = hbuf + p * HB_PAR + l * HB_SLOT;
#pragma unroll
                for (int e = 0; e < 4; ++e)
                    hdst[(grp * 4 + e) * HB_ROW + sub] = hn[e];
            }
            if (l == L_ - 1) {
                float4 v = make_float4(hn[0], hn[1], hn[2], hn[3]);
                *reinterpret_cast<float4*>(g_h3 + (long)(t * 16 + sub) * B_ + b0) = v;
            }
        }
        __syncthreads();
    }
}

// =====================================================================
// MLP phase 1: partial hid sums over NCHUNK chunks of 200 rows.
// =====================================================================
__global__ void __launch_bounds__(256) mlp1_kernel(const float* __restrict__ W1)
{
    __shared__ float4 W1s[200 * 16];   // [mm][j4], 51.2 KB
    const int chunk = blockIdx.y;
    const int m0 = chunk * 200;
    {
        float* w = reinterpret_cast<float*>(W1s);
        for (int idx = threadIdx.x; idx < 200 * MLP_HID; idx += blockDim.x) {
            int mm = idx >> 6, j = idx & 63;
            w[idx] = W1[j * MLP_IN + m0 + mm];
        }
    }
    __syncthreads();

    const int jq = threadIdx.x & 3;
    const int bq = threadIdx.x >> 2;
    const int b0 = blockIdx.x * 256 + bq * 4;

    ull acc[8][4];
#pragma unroll
    for (int jp = 0; jp < 8; ++jp)
#pragma unroll
        for (int e = 0; e < 4; ++e) acc[jp][e] = 0ull;

    for (int mm = 0; mm < 200; ++mm) {
        float4 f = *reinterpret_cast<const float4*>(g_h3 + (long)(m0 + mm) * B_ + b0);
        ull f2[4] = { pack2(f.x, f.x), pack2(f.y, f.y), pack2(f.z, f.z), pack2(f.w, f.w) };
#pragma unroll
        for (int j4 = 0; j4 < 4; ++j4) {
            ulonglong2 wp = *reinterpret_cast<const ulonglong2*>(&W1s[mm * 16 + jq * 4 + j4]);
#pragma unroll
            for (int e = 0; e < 4; ++e) {
                acc[j4 * 2 + 0][e] = ffma2(wp.x, f2[e], acc[j4 * 2 + 0][e]);
                acc[j4 * 2 + 1][e] = ffma2(wp.y, f2[e], acc[j4 * 2 + 1][e]);
            }
        }
    }
#pragma unroll
    for (int jp = 0; jp < 8; ++jp) {
        float v0[4], v1[4];
#pragma unroll
        for (int e = 0; e < 4; ++e) unpack2(acc[jp][e], v0[e], v1[e]);
        int j = jq * 16 + jp * 2;
        *reinterpret_cast<float4*>(g_partial + ((long)chunk * MLP_HID + j) * B_ + b0) =
            make_float4(v0[0], v0[1], v0[2], v0[3]);
        *reinterpret_cast<float4*>(g_partial + ((long)chunk * MLP_HID + j + 1) * B_ + b0) =
            make_float4(v1[0], v1[1], v1[2], v1[3]);
    }
}

// =====================================================================
// MLP phase 2: reduce chunks, bias+relu, W2, write out [B, 28].
// =====================================================================
__global__ void __launch_bounds__(256) mlp2_kernel(
    const float* __restrict__ W2,   // [28, 64]
    const float* __restrict__ b1,   // [64]
    const float* __restrict__ b2,   // [28]
    float* __restrict__ out)        // [B, 28]
{
    __shared__ float W2s[MLP_OUT * MLP_HID];
    __shared__ float b1s[MLP_HID];
    __shared__ float b2s[MLP_OUT];
    for (int idx = threadIdx.x; idx < MLP_OUT * MLP_HID; idx += blockDim.x)
        W2s[idx] = W2[idx];
    if (threadIdx.x < MLP_HID) b1s[threadIdx.x] = b1[threadIdx.x];
    if (threadIdx.x < MLP_OUT) b2s[threadIdx.x] = b2[threadIdx.x];
    __syncthreads();

    const int b = blockIdx.x * 256 + threadIdx.x;
    float hid[MLP_HID];
#pragma unroll
    for (int j = 0; j < MLP_HID; ++j) hid[j] = b1s[j];

    for (int ch = 0; ch < NCHUNK; ++ch) {
#pragma unroll
        for (int j = 0; j < MLP_HID; ++j)
            hid[j] += g_partial[((long)ch * MLP_HID + j) * B_ + b];
    }
#pragma unroll
    for (int j = 0; j < MLP_HID; ++j) hid[j] = fmaxf(hid[j], 0.0f);

#pragma unroll
    for (int o = 0; o < MLP_OUT; ++o) {
        float a = b2s[o];
#pragma unroll
        for (int j = 0; j < MLP_HID; ++j)
            a = fmaf(hid[j], W2s[o * MLP_HID + j], a);
        out[(long)b * MLP_OUT + o] = a;
    }
}

// =====================================================================
extern "C" void kernel_launch(void* const* d_in, const int* in_sizes, int n_in,
                              void* d_out, int out_size)
{
    const float* x        = (const float*)d_in[0];
    const float* Wih0     = (const float*)d_in[1];
    const float* Wih_rest = (const float*)d_in[2];
    const float* Whh      = (const float*)d_in[3];
    const float* bih      = (const float*)d_in[4];
    const float* bhh      = (const float*)d_in[5];
    const float* W1       = (const float*)d_in[6];
    const float* b1       = (const float*)d_in[7];
    const float* W2       = (const float*)d_in[8];
    const float* b2       = (const float*)d_in[9];
    float* out = (float*)d_out;

    lstm_kernel<<<1024, 128>>>(x, Wih0, Wih_rest, Whh, bih, bhh);
    mlp1_kernel<<<dim3(32, NCHUNK), 256>>>(W1);
    mlp2_kernel<<<32, 256>>>(W2, b1, b2, out);
}

// round 16
// speedup vs baseline: 1.2353x; 1.0075x over previous
#include <cuda_runtime.h>
#include <cuda_bf16.h>

#define B_  8192
#define T_  200
#define IN_ 4
#define H_  16
#define L_  4
#define MLP_IN  (H_ * T_)   // 3200
#define MLP_HID 64
#define MLP_OUT 28
#define NCHUNK  16          // mlp1 K-chunks (200 rows each)

typedef unsigned long long ull;

// ---------------- scratch (no allocations allowed) ----------------
__device__ float g_h3[(long)MLP_IN * B_];                 // [m][b]
__device__ float g_partial[NCHUNK * MLP_HID * B_];        // [chunk][j][b]

// ---------------- packed f32x2 helpers ----------------
__device__ __forceinline__ ull pack2(float lo, float hi) {
    ull r; asm("mov.b64 %0, {%1, %2};" : "=l"(r) : "f"(lo), "f"(hi)); return r;
}
__device__ __forceinline__ void unpack2(ull v, float& lo, float& hi) {
    asm("mov.b64 {%0, %1}, %2;" : "=f"(lo), "=f"(hi) : "l"(v));
}
__device__ __forceinline__ ull ffma2(ull a, ull b, ull c) {
    ull d; asm("fma.rn.f32x2 %0, %1, %2, %3;" : "=l"(d) : "l"(a), "l"(b), "l"(c)); return d;
}

// ---------------- activations via MUFU.TANH (1 MUFU each) ------------
__device__ __forceinline__ float tanh_hw(float x) {
    float y; asm("tanh.approx.f32 %0, %1;" : "=f"(y) : "f"(x)); return y;
}
__device__ __forceinline__ float sigmoid_hw(float x) {
    return fmaf(tanh_hw(0.5f * x), 0.5f, 0.5f);
}

// h ring: float hbuf[parity(2)][layer(4)][step(2)][eg(8)][row 20]
#define HB_STEP 160
#define HB_L2   (2 * HB_STEP)
#define HB_PAR2 (4 * HB_L2)
#define HB_TOTAL (2 * HB_PAR2)          // 2560 floats
// x: float xbuf[parity(2)][eg(8)][8] : floats 0-3 = x(t0), 4-7 = x(t0+1)
#define XB_PAR  64
#define XB_TOTAL (2 * XB_PAR)

// paired weight layouts (ulonglong2 = 4 consecutive k as two f32x2 pairs)
#define WINP_N  (L_ * 4 * 4 * 16)   // input-projection, all gates (16 KB)
#define WRECP_N (L_ * 2 * 4 * 16)   // recurrent, gates 2..3       (8 KB)
#define BIASP_N (L_ * 2 * 16)       // bias pairs                  (2 KB)

// =====================================================================
// Layer-pipelined LSTM, TWO timesteps per barrier interval.
// CTA = 4 warps = 4 layers, 8 batch elems. Warp l computes
// t = 2(i-l), 2(i-l)+1 at interval i; layer l-1 produced those h's in
// interval i-1. Step1's recurrent input is own step0 (syncwarp only).
// Gates 0..1 recurrent weights in registers; rest in smem (paired
// LDS.128). regs <= 128 -> 4 CTAs/SM. 1024 CTAs x 128 threads.
// =====================================================================
__global__ void __launch_bounds__(128, 4) lstm_kernel(
    const float* __restrict__ x,         // [B, T, IN]
    const float* __restrict__ Wih0,      // [64, 4]
    const float* __restrict__ Wih_rest,  // [3, 64, 16]
    const float* __restrict__ Whh,       // [4, 64, 16]
    const float* __restrict__ bih,       // [4, 64]
    const float* __restrict__ bhh)       // [4, 64]
{
    __shared__ __align__(16) float hbuf[HB_TOTAL];
    __shared__ __align__(16) float xbuf[XB_TOTAL];
    __shared__ __align__(16) ulonglong2 WinP[WINP_N];
    __shared__ __align__(16) ulonglong2 WrecP[WRECP_N];
    __shared__ __align__(16) ulonglong2 biasP2[BIASP_N];

    const int wid  = threadIdx.x >> 5;
    const int lane = threadIdx.x & 31;
    const int sub  = lane & 15;
    const int grp  = lane >> 4;
    const int l    = (wid + (int)blockIdx.x) & 3;        // layer rotation
    const int b0c  = (int)blockIdx.x * 8;                // CTA batch base
    const int b0   = b0c + grp * 4;                      // elems b0..b0+3

    for (int i = threadIdx.x; i < HB_TOTAL; i += blockDim.x) hbuf[i] = 0.0f;
    for (int i = threadIdx.x; i < XB_TOTAL; i += blockDim.x) xbuf[i] = 0.0f;

    // ---- stage WinP ----
    for (int idx = threadIdx.x; idx < WINP_N; idx += blockDim.x) {
        int j  = idx & 15;
        int kc = (idx >> 4) & 3;
        int g  = (idx >> 6) & 3;
        int li = idx >> 8;
        float4 v = make_float4(0.f, 0.f, 0.f, 0.f);
        if (li == 0) {
            if (kc == 0) v = *reinterpret_cast<const float4*>(Wih0 + (g * 16 + j) * IN_);
        } else {
            v = *reinterpret_cast<const float4*>(
                Wih_rest + (li - 1) * 1024 + (g * 16 + j) * 16 + kc * 4);
        }
        WinP[idx] = *reinterpret_cast<ulonglong2*>(&v);
    }
    // ---- stage WrecP (gates 2..3) ----
    for (int idx = threadIdx.x; idx < WRECP_N; idx += blockDim.x) {
        int j  = idx & 15;
        int kc = (idx >> 4) & 3;
        int gp = (idx >> 6) & 1;
        int li = idx >> 7;
        float4 v = *reinterpret_cast<const float4*>(
            Whh + li * 1024 + ((gp + 2) * 16 + j) * 16 + kc * 4);
        WrecP[idx] = *reinterpret_cast<ulonglong2*>(&v);
    }
    // ---- stage biasP2 ----
    for (int idx = threadIdx.x; idx < BIASP_N; idx += blockDim.x) {
        int j  = idx & 15;
        int gp = (idx >> 4) & 1;
        int li = idx >> 5;
        ulonglong2 v;
        v.x = pack2(bih[li * 64 + (2 * gp + 0) * 16 + j] + bhh[li * 64 + (2 * gp + 0) * 16 + j], 0.0f);
        v.y = pack2(bih[li * 64 + (2 * gp + 1) * 16 + j] + bhh[li * 64 + (2 * gp + 1) * 16 + j], 0.0f);
        biasP2[idx] = v;
    }

    // ---- gates 0..1 recurrent weights into registers ----
    ull Wrec[2][8];   // [gate][kpair]
#pragma unroll
    for (int g = 0; g < 2; ++g) {
        const float* rsrc = Whh + l * 1024 + (g * 16 + sub) * 16;
#pragma unroll
        for (int kc = 0; kc < 4; ++kc) {
            ulonglong2 v = *reinterpret_cast<const ulonglong2*>(rsrc + kc * 4);
            Wrec[g][2 * kc] = v.x; Wrec[g][2 * kc + 1] = v.y;
        }
    }

    // initial x(0), x(1) into xbuf parity 1 (interval 0 reads 1-p = 1)
    if (threadIdx.x < 8) {
        float4 v0 = *reinterpret_cast<const float4*>(x + (long)(b0c + threadIdx.x) * (T_ * IN_));
        float4 v1 = *reinterpret_cast<const float4*>(x + (long)(b0c + threadIdx.x) * (T_ * IN_) + IN_);
        *reinterpret_cast<float4*>(xbuf + XB_PAR + threadIdx.x * 8)     = v0;
        *reinterpret_cast<float4*>(xbuf + XB_PAR + threadIdx.x * 8 + 4) = v1;
    }

    float c_own[4] = {0.0f, 0.0f, 0.0f, 0.0f};
    const ulonglong2* const winL  = WinP  + (l * 4) * 4 * 16;  // [g][kc][j]
    const ulonglong2* const wrecL = WrecP + (l * 2) * 4 * 16;  // [gp][kc][j]
    const ulonglong2* const biasL = biasP2 + (l * 2) * 16;     // [gp][j]
    __syncthreads();

    const int NI = T_ / 2 + L_ - 1;   // 103 intervals
    for (int i = 0; i < NI; ++i) {
        const int p = i & 1;
        const int q = 1 - p;
        const int t0 = 2 * (i - l);
        const bool active = (i >= l) && (t0 < T_);

        if (active) {
            // warp 0 prefetches x(t0+2), x(t0+3) for next interval
            if (l == 0 && lane < 8 && t0 + 2 < T_) {
                const float* xsrcg = x + (long)(b0c + lane) * (T_ * IN_) + (t0 + 2) * IN_;
                float4 v0 = *reinterpret_cast<const float4*>(xsrcg);
                float4 v1 = *reinterpret_cast<const float4*>(xsrcg + IN_);
                *reinterpret_cast<float4*>(xbuf + p * XB_PAR + lane * 8)     = v0;
                *reinterpret_cast<float4*>(xbuf + p * XB_PAR + lane * 8 + 4) = v1;
            }

#pragma unroll
            for (int s = 0; s < 2; ++s) {
                ull acc[4][4];   // [gate][e], halves = (even-k, odd-k)
                {
                    ulonglong2 b01 = biasL[0 * 16 + sub];
                    ulonglong2 b23 = biasL[1 * 16 + sub];
#pragma unroll
                    for (int e = 0; e < 4; ++e) {
                        acc[0][e] = b01.x; acc[1][e] = b01.y;
                        acc[2][e] = b23.x; acc[3][e] = b23.y;
                    }
                }

                // ---- input projection ----
                if (l == 0) {
                    const float* xsrc = xbuf + q * XB_PAR + s * 4;
#pragma unroll
                    for (int e = 0; e < 4; ++e) {
                        ulonglong2 xv = *reinterpret_cast<const ulonglong2*>(
                            xsrc + (grp * 4 + e) * 8);
#pragma unroll
                        for (int g = 0; g < 4; ++g) {
                            ulonglong2 wv = winL[(g * 4 + 0) * 16 + sub];
                            acc[g][e] = ffma2(wv.x, xv.x, acc[g][e]);
                            acc[g][e] = ffma2(wv.y, xv.y, acc[g][e]);
                        }
                    }
                } else {
                    const float* hsrc = hbuf + q * HB_PAR2 + (l - 1) * HB_L2 + s * HB_STEP;
#pragma unroll
                    for (int kc = 0; kc < 4; ++kc) {
                        ulonglong2 hv[4];
#pragma unroll
                        for (int e = 0; e < 4; ++e)
                            hv[e] = *reinterpret_cast<const ulonglong2*>(
                                hsrc + (grp * 4 + e) * 20 + kc * 4);
#pragma unroll
                        for (int g = 0; g < 4; ++g) {
                            ulonglong2 wv = winL[(g * 4 + kc) * 16 + sub];
#pragma unroll
                            for (int e = 0; e < 4; ++e) {
                                acc[g][e] = ffma2(wv.x, hv[e].x, acc[g][e]);
                                acc[g][e] = ffma2(wv.y, hv[e].y, acc[g][e]);
                            }
                        }
                    }
                }

                // ---- recurrent projection ----
                {
                    // s=0: own layer step1 of prev interval; s=1: own step0 (this interval)
                    const float* hsrc = (s == 0)
                        ? hbuf + q * HB_PAR2 + l * HB_L2 + 1 * HB_STEP
                        : hbuf + p * HB_PAR2 + l * HB_L2 + 0 * HB_STEP;
#pragma unroll
                    for (int kc = 0; kc < 4; ++kc) {
                        ulonglong2 hv[4];
#pragma unroll
                        for (int e = 0; e < 4; ++e)
                            hv[e] = *reinterpret_cast<const ulonglong2*>(
                                hsrc + (grp * 4 + e) * 20 + kc * 4);
#pragma unroll
                        for (int g = 0; g < 2; ++g)
#pragma unroll
                            for (int e = 0; e < 4; ++e) {
                                acc[g][e] = ffma2(Wrec[g][2 * kc],     hv[e].x, acc[g][e]);
                                acc[g][e] = ffma2(Wrec[g][2 * kc + 1], hv[e].y, acc[g][e]);
                            }
#pragma unroll
                        for (int gp = 0; gp < 2; ++gp) {
                            ulonglong2 wv = wrecL[(gp * 4 + kc) * 16 + sub];
#pragma unroll
                            for (int e = 0; e < 4; ++e) {
                                acc[gp + 2][e] = ffma2(wv.x, hv[e].x, acc[gp + 2][e]);
                                acc[gp + 2][e] = ffma2(wv.y, hv[e].y, acc[gp + 2][e]);
                            }
                        }
                    }
                }

                // ---- horizontal add + activations + state update ----
                float hn[4];
#pragma unroll
                for (int e = 0; e < 4; ++e) {
                    float lo, hi, ai, af, ag, ao;
                    unpack2(acc[0][e], lo, hi); ai = lo + hi;
                    unpack2(acc[1][e], lo, hi); af = lo + hi;
                    unpack2(acc[2][e], lo, hi); ag = lo + hi;
                    unpack2(acc[3][e], lo, hi); ao = lo + hi;
                    float iv = sigmoid_hw(ai);
                    float fv = sigmoid_hw(af);
                    float gv = tanh_hw(ag);
                    float ov = sigmoid_hw(ao);
                    float cv = fmaf(fv, c_own[e], iv * gv);
                    c_own[e] = cv;
                    hn[e] = ov * tanh_hw(cv);
                }

                // ---- publish new h into [p][l][s] ----
                __syncwarp();
                {
                    float* hdst = hbuf + p * HB_PAR2 + l * HB_L2 + s * HB_STEP;
#pragma unroll
                    for (int e = 0; e < 4; ++e)
                        hdst[(grp * 4 + e) * 20 + sub] = hn[e];
                }
                __syncwarp();

                if (l == L_ - 1) {
                    float4 v = make_float4(hn[0], hn[1], hn[2], hn[3]);
                    *reinterpret_cast<float4*>(g_h3 + (long)((t0 + s) * 16 + sub) * B_ + b0) = v;
                }
            }
        }
        __syncthreads();
    }
}

// =====================================================================
// MLP phase 1: partial hid sums over NCHUNK chunks of 200 rows.
// =====================================================================
__global__ void __launch_bounds__(256) mlp1_kernel(const float* __restrict__ W1)
{
    __shared__ float4 W1s[200 * 16];   // [mm][j4], 51.2 KB
    const int chunk = blockIdx.y;
    const int m0 = chunk * 200;
    {
        float* w = reinterpret_cast<float*>(W1s);
        for (int idx = threadIdx.x; idx < 200 * MLP_HID; idx += blockDim.x) {
            int mm = idx >> 6, j = idx & 63;
            w[idx] = W1[j * MLP_IN + m0 + mm];
        }
    }
    __syncthreads();

    const int jq = threadIdx.x & 3;
    const int bq = threadIdx.x >> 2;
    const int b0 = blockIdx.x * 256 + bq * 4;

    ull acc[8][4];
#pragma unroll
    for (int jp = 0; jp < 8; ++jp)
#pragma unroll
        for (int e = 0; e < 4; ++e) acc[jp][e] = 0ull;

    for (int mm = 0; mm < 200; ++mm) {
        float4 f = *reinterpret_cast<const float4*>(g_h3 + (long)(m0 + mm) * B_ + b0);
        ull f2[4] = { pack2(f.x, f.x), pack2(f.y, f.y), pack2(f.z, f.z), pack2(f.w, f.w) };
#pragma unroll
        for (int j4 = 0; j4 < 4; ++j4) {
            ulonglong2 wp = *reinterpret_cast<const ulonglong2*>(&W1s[mm * 16 + jq * 4 + j4]);
#pragma unroll
            for (int e = 0; e < 4; ++e) {
                acc[j4 * 2 + 0][e] = ffma2(wp.x, f2[e], acc[j4 * 2 + 0][e]);
                acc[j4 * 2 + 1][e] = ffma2(wp.y, f2[e], acc[j4 * 2 + 1][e]);
            }
        }
    }
#pragma unroll
    for (int jp = 0; jp < 8; ++jp) {
        float v0[4], v1[4];
#pragma unroll
        for (int e = 0; e < 4; ++e) unpack2(acc[jp][e], v0[e], v1[e]);
        int j = jq * 16 + jp * 2;
        *reinterpret_cast<float4*>(g_partial + ((long)chunk * MLP_HID + j) * B_ + b0) =
            make_float4(v0[0], v0[1], v0[2], v0[3]);
        *reinterpret_cast<float4*>(g_partial + ((long)chunk * MLP_HID + j + 1) * B_ + b0) =
            make_float4(v1[0], v1[1], v1[2], v1[3]);
    }
}

// =====================================================================
// MLP phase 2: reduce chunks, bias+relu, W2, write out [B, 28].
// =====================================================================
__global__ void __launch_bounds__(256) mlp2_kernel(
    const float* __restrict__ W2,   // [28, 64]
    const float* __restrict__ b1,   // [64]
    const float* __restrict__ b2,   // [28]
    float* __restrict__ out)        // [B, 28]
{
    __shared__ float W2s[MLP_OUT * MLP_HID];
    __shared__ float b1s[MLP_HID];
    __shared__ float b2s[MLP_OUT];
    for (int idx = threadIdx.x; idx < MLP_OUT * MLP_HID; idx += blockDim.x)
        W2s[idx] = W2[idx];
    if (threadIdx.x < MLP_HID) b1s[threadIdx.x] = b1[threadIdx.x];
    if (threadIdx.x < MLP_OUT) b2s[threadIdx.x] = b2[threadIdx.x];
    __syncthreads();

    const int b = blockIdx.x * 256 + threadIdx.x;
    float hid[MLP_HID];
#pragma unroll
    for (int j = 0; j < MLP_HID; ++j) hid[j] = b1s[j];

    for (int ch = 0; ch < NCHUNK; ++ch) {
#pragma unroll
        for (int j = 0; j < MLP_HID; ++j)
            hid[j] += g_partial[((long)ch * MLP_HID + j) * B_ + b];
    }
#pragma unroll
    for (int j = 0; j < MLP_HID; ++j) hid[j] = fmaxf(hid[j], 0.0f);

#pragma unroll
    for (int o = 0; o < MLP_OUT; ++o) {
        float a = b2s[o];
#pragma unroll
        for (int j = 0; j < MLP_HID; ++j)
            a = fmaf(hid[j], W2s[o * MLP_HID + j], a);
        out[(long)b * MLP_OUT + o] = a;
    }
}

// =====================================================================
extern "C" void kernel_launch(void* const* d_in, const int* in_sizes, int n_in,
                              void* d_out, int out_size)
{
    const float* x        = (const float*)d_in[0];
    const float* Wih0     = (const float*)d_in[1];
    const float* Wih_rest = (const float*)d_in[2];
    const float* Whh      = (const float*)d_in[3];
    const float* bih      = (const float*)d_in[4];
    const float* bhh      = (const float*)d_in[5];
    const float* W1       = (const float*)d_in[6];
    const float* b1       = (const float*)d_in[7];
    const float* W2       = (const float*)d_in[8];
    const float* b2       = (const float*)d_in[9];
    float* out = (float*)d_out;

    lstm_kernel<<<1024, 128>>>(x, Wih0, Wih_rest, Whh, bih, bhh);
    mlp1_kernel<<<dim3(32, NCHUNK), 256>>>(W1);
    mlp2_kernel<<<32, 256>>>(W2, b1, b2, out);
}